// round 4
// baseline (speedup 1.0000x reference)
#include <cuda_runtime.h>

typedef unsigned long long ull;

// Problem: X[8,256,128], W1[128,128], W2[128,128], v[128] -> out[8,256,256]
#define BB   8
#define DD   256
#define DIM  128
#define ROWS 2048

// Scratch. Layouts chosen for k2's access pattern:
//  g_EaT : [b][m][d]            (k2 stages j-quads with one LDG.128/thread)
//  g_Ec4 : [b][g=m/4][k][m%4]   (k2 reads 4 m-values per g as one LDG.128)
__device__ float g_EaT[BB * DIM * DD];
__device__ float g_Ec4[BB * 32 * DD * 4 + 4096];   // padded for prefetch tail
__device__ float g_Vsum;

// ---- packed f32x2 helpers (Blackwell) --------------------------------------
__device__ __forceinline__ ull fma2(ull a, ull b, ull c) {
    ull d; asm("fma.rn.f32x2 %0,%1,%2,%3;" : "=l"(d) : "l"(a), "l"(b), "l"(c)); return d;
}
__device__ __forceinline__ ull mul2(ull a, ull b) {
    ull d; asm("mul.rn.f32x2 %0,%1,%2;" : "=l"(d) : "l"(a), "l"(b)); return d;
}
__device__ __forceinline__ ull dup2(float x) {
    ull d; asm("mov.b64 %0,{%1,%1};" : "=l"(d) : "f"(x)); return d;
}
__device__ __forceinline__ float2 unpk(ull a) {
    float2 r; asm("mov.b64 {%0,%1},%2;" : "=f"(r.x), "=f"(r.y) : "l"(a)); return r;
}
__device__ __forceinline__ ull pk(float x, float y) {
    ull d; asm("mov.b64 %0,{%1,%2};" : "=l"(d) : "f"(x), "f"(y)); return d;
}
__device__ __forceinline__ float frcp(float x) {
    float r; asm("rcp.approx.f32 %0,%1;" : "=f"(r) : "f"(x)); return r;
}

// ---------------------------------------------------------------------------
// Kernel 1: grid = 256 (128 row-tiles of 16 x 2 mats), 512 threads, occ 2.
// Thread = (m, 4 rows). FFMA2 packed over k-pairs. Direct scatter stores into
// k2-friendly layouts (scatter traffic <= 8MB effective: negligible).
// Block 0 additionally computes g_Vsum.
// ---------------------------------------------------------------------------
#define W_STRIDE 132
#define K1_SMEM ((DIM * W_STRIDE + 16 * DIM) * 4)   // 67584 + 8192 B

__global__ void __launch_bounds__(512, 2) k1_gemm_exp(
    const float* __restrict__ X,
    const float* __restrict__ W1,
    const float* __restrict__ W2,
    const float* __restrict__ v)
{
    extern __shared__ float sm[];
    float* Ws = sm;                        // 128 x 132
    float* Xs = sm + DIM * W_STRIDE;       // 16 x 128

    const int t       = threadIdx.x;
    const int mat     = blockIdx.x & 1;
    const int rowbase = (blockIdx.x >> 1) * 16;
    const float* W = mat ? W2 : W1;

    if (blockIdx.x == 0 && t < 32) {       // Vsum side-job (warp 0, block 0)
        float s = v[t] + v[t + 32] + v[t + 64] + v[t + 96];
        #pragma unroll
        for (int o = 16; o; o >>= 1) s += __shfl_xor_sync(0xffffffffu, s, o);
        if (t == 0) g_Vsum = s;
    }

    #pragma unroll
    for (int i = t; i < DIM * 32; i += 512) {           // W: 4096 float4
        int m  = i >> 5;
        int k4 = i & 31;
        *(float4*)&Ws[m * W_STRIDE + k4 * 4] = ((const float4*)W)[i];
    }
    ((float4*)Xs)[t] = ((const float4*)X)[rowbase * 32 + t];   // 16 rows
    __syncthreads();

    const int m  = t & 127;
    const int r0 = (t >> 7) * 4;            // 4 rows per thread

    ull acc[4];
    #pragma unroll
    for (int r = 0; r < 4; r++) acc[r] = dup2(0.0f);

    #pragma unroll 8
    for (int k4 = 0; k4 < 32; k4++) {
        ulonglong2 w = *(const ulonglong2*)&Ws[m * W_STRIDE + k4 * 4];
        #pragma unroll
        for (int r = 0; r < 4; r++) {
            ulonglong2 x = *(const ulonglong2*)&Xs[(r0 + r) * DIM + k4 * 4];
            acc[r] = fma2(w.x, x.x, acc[r]);
            acc[r] = fma2(w.y, x.y, acc[r]);
        }
    }

    const int b  = rowbase >> 8;
    const int d0 = (rowbase & 255) + r0;

    if (mat == 0) {
        #pragma unroll
        for (int r = 0; r < 4; r++) {
            float2 a = unpk(acc[r]);
            g_EaT[(size_t)(b * DIM + m) * DD + d0 + r] = __expf(2.0f * (a.x + a.y));
        }
    } else {
        const size_t base = ((size_t)(b * 32 + (m >> 2)) * DD) * 4 + (m & 3);
        #pragma unroll
        for (int r = 0; r < 4; r++) {
            float2 a = unpk(acc[r]);
            g_Ec4[base + (size_t)(d0 + r) * 4] = __expf(2.0f * (a.x + a.y));
        }
    }
}

// ---------------------------------------------------------------------------
// Kernel 2: grid = 1024 (b x 64 j-groups x 2 k-tiles), 128 threads, occ 8
// (<=64 regs). Thread = 1 k, 4 j (two packed f32x2 pairs). Per g (4 m):
//   1 LDG.128 (Ec quad, double-buffered) + 4 broadcast LDS.128 (Ea j-quads)
//   + 2 uniform LDS.128 (v-dups) + 28 FMA2 + 4 RCP  -> FMA-pipe bound.
// 4-way rational combine: out = Vsum - 2*sum v_m/(Ea*Ec+1), 1 rcp per 4 m.
// ---------------------------------------------------------------------------
__global__ void __launch_bounds__(128, 8) k2_pairwise(
    const float* __restrict__ v,
    float* __restrict__ out)
{
    __shared__ __align__(16) float4 EaTf4[DIM];   // [m] -> (a_j0,a_j1,a_j2,a_j3)
    __shared__ __align__(16) float2 vD[DIM];      // duplicated v

    const int t   = threadIdx.x;
    const int bid = blockIdx.x;
    const int kt  = bid & 1;
    const int jg  = (bid >> 1) & 63;
    const int b   = bid >> 7;
    const int j0  = jg * 4;
    const int k   = kt * 128 + t;

    EaTf4[t] = *(const float4*)&g_EaT[(size_t)(b * DIM + t) * DD + j0];
    {
        float vv = v[t];
        vD[t] = make_float2(vv, vv);
    }
    __syncthreads();

    const float Vsum = g_Vsum;
    const ull ONE2 = dup2(1.0f);
    ull acc0 = dup2(0.0f), acc1 = dup2(0.0f);

    const float* ecb = g_Ec4 + (size_t)b * 32 * DD * 4 + k * 4;
    float4 E = *(const float4*)ecb;               // g = 0

    #pragma unroll 4
    for (int g = 0; g < 32; g++) {
        float4 En = *(const float4*)(ecb + (size_t)(g + 1) * (DD * 4)); // padded tail
        ull ec0 = dup2(E.x), ec1 = dup2(E.y), ec2 = dup2(E.z), ec3 = dup2(E.w);

        const ulonglong2* eap = (const ulonglong2*)(EaTf4 + 4 * g);
        ulonglong2 ea0 = eap[0], ea1 = eap[1], ea2 = eap[2], ea3 = eap[3];
        ulonglong2 vab = ((const ulonglong2*)vD)[2 * g];       // (v0v0, v1v1)
        ulonglong2 vcd = ((const ulonglong2*)vD)[2 * g + 1];   // (v2v2, v3v3)

        {   // j-pair 0 (j0,j1): low halves of ea quads
            ull q0 = fma2(ea0.x, ec0, ONE2);
            ull q1 = fma2(ea1.x, ec1, ONE2);
            ull q2 = fma2(ea2.x, ec2, ONE2);
            ull q3 = fma2(ea3.x, ec3, ONE2);
            ull d01 = mul2(q0, q1), d23 = mul2(q2, q3);
            ull n01 = mul2(vab.x, q1); n01 = fma2(vab.y, q0, n01);
            ull n23 = mul2(vcd.x, q3); n23 = fma2(vcd.y, q2, n23);
            ull den = mul2(d01, d23);
            ull num = mul2(n01, d23); num = fma2(n23, d01, num);
            float2 dd = unpk(den);
            ull rr = pk(frcp(dd.x), frcp(dd.y));
            acc0 = fma2(num, rr, acc0);
        }
        {   // j-pair 1 (j2,j3): high halves
            ull q0 = fma2(ea0.y, ec0, ONE2);
            ull q1 = fma2(ea1.y, ec1, ONE2);
            ull q2 = fma2(ea2.y, ec2, ONE2);
            ull q3 = fma2(ea3.y, ec3, ONE2);
            ull d01 = mul2(q0, q1), d23 = mul2(q2, q3);
            ull n01 = mul2(vab.x, q1); n01 = fma2(vab.y, q0, n01);
            ull n23 = mul2(vcd.x, q3); n23 = fma2(vcd.y, q2, n23);
            ull den = mul2(d01, d23);
            ull num = mul2(n01, d23); num = fma2(n23, d01, num);
            float2 dd = unpk(den);
            ull rr = pk(frcp(dd.x), frcp(dd.y));
            acc1 = fma2(num, rr, acc1);
        }
        E = En;
    }

    float* obase = out + (size_t)(b * DD + j0) * DD + k;
    float2 a0 = unpk(acc0), a1 = unpk(acc1);
    obase[0 * DD] = fmaf(-2.0f, a0.x, Vsum);
    obase[1 * DD] = fmaf(-2.0f, a0.y, Vsum);
    obase[2 * DD] = fmaf(-2.0f, a1.x, Vsum);
    obase[3 * DD] = fmaf(-2.0f, a1.y, Vsum);
}

// ---------------------------------------------------------------------------
extern "C" void kernel_launch(void* const* d_in, const int* in_sizes, int n_in,
                              void* d_out, int out_size)
{
    const float* X  = (const float*)d_in[0];
    const float* W1 = (const float*)d_in[1];
    const float* W2 = (const float*)d_in[2];
    const float* v  = (const float*)d_in[3];
    float* out      = (float*)d_out;

    cudaFuncSetAttribute(k1_gemm_exp,
                         cudaFuncAttributeMaxDynamicSharedMemorySize, K1_SMEM);

    k1_gemm_exp<<<256, 512, K1_SMEM>>>(X, W1, W2, v);
    k2_pairwise<<<1024, 128>>>(v, out);
}

// round 5
// speedup vs baseline: 1.0756x; 1.0756x over previous
#include <cuda_runtime.h>

typedef unsigned long long ull;

// Problem: X[8,256,128], W1[128,128], W2[128,128], v[128] -> out[8,256,256]
#define BB   8
#define DD   256
#define DIM  128

// Scratch layouts tuned for k2:
//  g_EaT : [b][m][d]           (k2 stages j-quads with one LDG.128/thread)
//  g_Ec4 : [b][g=m/4][k][m%4]  (k2 streams one float4 per g per thread)
__device__ float g_EaT[BB * DIM * DD];
__device__ float g_Ec4[BB * 32 * DD * 4 + 8192];
__device__ float g_Vsum;

// ---- packed f32x2 helpers (Blackwell) --------------------------------------
__device__ __forceinline__ ull fma2(ull a, ull b, ull c) {
    ull d; asm("fma.rn.f32x2 %0,%1,%2,%3;" : "=l"(d) : "l"(a), "l"(b), "l"(c)); return d;
}
__device__ __forceinline__ ull mul2(ull a, ull b) {
    ull d; asm("mul.rn.f32x2 %0,%1,%2;" : "=l"(d) : "l"(a), "l"(b)); return d;
}
__device__ __forceinline__ ull dup2(float x) {
    ull d; asm("mov.b64 %0,{%1,%1};" : "=l"(d) : "f"(x)); return d;
}
__device__ __forceinline__ float2 unpk(ull a) {
    float2 r; asm("mov.b64 {%0,%1},%2;" : "=f"(r.x), "=f"(r.y) : "l"(a)); return r;
}
__device__ __forceinline__ ull pk(float x, float y) {
    ull d; asm("mov.b64 %0,{%1,%2};" : "=l"(d) : "f"(x), "f"(y)); return d;
}
__device__ __forceinline__ float frcp(float x) {
    float r; asm("rcp.approx.f32 %0,%1;" : "=f"(r) : "f"(x)); return r;
}
__device__ __forceinline__ void cp16(unsigned smem_dst, const void* gsrc) {
    asm volatile("cp.async.cg.shared.global [%0], [%1], 16;"
                 :: "r"(smem_dst), "l"(gsrc) : "memory");
}
__device__ __forceinline__ void cp_commit() {
    asm volatile("cp.async.commit_group;" ::: "memory");
}
template<int N> __device__ __forceinline__ void cp_wait() {
    asm volatile("cp.async.wait_group %0;" :: "n"(N) : "memory");
}

// ---------------------------------------------------------------------------
// Kernel 1: grid = 128 (64 tiles of 32 rows x 2 mats), 512 threads, 1/SM.
// FFMA2 main loop; outputs written through conflict-free smem transposes so
// every STG is a coalesced STG.128. Block 0 also computes g_Vsum.
// ---------------------------------------------------------------------------
#define W_STRIDE 132
#define K1_SMEM ((DIM * W_STRIDE + 32 * DIM) * 4)   // 67584 + 16384 B

__global__ void __launch_bounds__(512, 1) k1_gemm_exp(
    const float* __restrict__ X,
    const float* __restrict__ W1,
    const float* __restrict__ W2,
    const float* __restrict__ v)
{
    extern __shared__ float sm[];
    float* Ws = sm;                        // 128 x 132 (also reused as Es)
    float* Xs = sm + DIM * W_STRIDE;       // 32 x 128

    const int t       = threadIdx.x;
    const int mat     = blockIdx.x & 1;
    const int rowbase = (blockIdx.x >> 1) * 32;
    const float* W = mat ? W2 : W1;

    if (blockIdx.x == 0 && t < 32) {       // Vsum side-job
        float s = v[t] + v[t + 32] + v[t + 64] + v[t + 96];
        #pragma unroll
        for (int o = 16; o; o >>= 1) s += __shfl_xor_sync(0xffffffffu, s, o);
        if (t == 0) g_Vsum = s;
    }

    #pragma unroll
    for (int i = t; i < DIM * 32; i += 512) {           // W: 4096 float4
        int m  = i >> 5;
        int k4 = i & 31;
        *(float4*)&Ws[m * W_STRIDE + k4 * 4] = ((const float4*)W)[i];
    }
    #pragma unroll
    for (int i = t; i < 1024; i += 512)                 // X: 32 rows
        ((float4*)Xs)[i] = ((const float4*)X)[rowbase * 32 + i];
    __syncthreads();

    const int m  = t & 127;
    const int r0 = (t >> 7) * 8;           // 8 rows per thread

    ull acc[8];
    #pragma unroll
    for (int r = 0; r < 8; r++) acc[r] = dup2(0.0f);

    #pragma unroll 4
    for (int k4 = 0; k4 < 32; k4++) {
        ulonglong2 w = *(const ulonglong2*)&Ws[m * W_STRIDE + k4 * 4];
        #pragma unroll
        for (int r = 0; r < 8; r++) {
            ulonglong2 x = *(const ulonglong2*)&Xs[(r0 + r) * DIM + k4 * 4];
            acc[r] = fma2(w.x, x.x, acc[r]);
            acc[r] = fma2(w.y, x.y, acc[r]);
        }
    }

    float val[8];
    #pragma unroll
    for (int r = 0; r < 8; r++) {
        float2 a = unpk(acc[r]);
        val[r] = __expf(2.0f * (a.x + a.y));
    }

    // Let k2 launch & run its independent prologue while we store.
    cudaTriggerProgrammaticLaunchCompletion();

    const int b  = rowbase >> 8;
    const int d0 = rowbase & 255;
    float* Es = Ws;
    __syncthreads();                       // done reading Ws/Xs

    if (mat == 0) {
        // Es[m][row] stride 33; banks (m + d) % 32 -> conflict-free writes
        #pragma unroll
        for (int r = 0; r < 8; r++) Es[m * 33 + (r0 + r)] = val[r];
        __syncthreads();
        #pragma unroll
        for (int it = 0; it < 2; it++) {
            int idx = t + it * 512;        // 1024 float4
            int mm = idx >> 3, dq = idx & 7;
            float4 o;                      // scalar reads (stride-33 rows)
            o.x = Es[mm * 33 + dq * 4 + 0];
            o.y = Es[mm * 33 + dq * 4 + 1];
            o.z = Es[mm * 33 + dq * 4 + 2];
            o.w = Es[mm * 33 + dq * 4 + 3];
            *(float4*)&g_EaT[(size_t)(b * DIM + mm) * DD + d0 + dq * 4] = o;
        }
    } else {
        // Es[k_local][m] stride 132; banks (4k + m) % 32 -> conflict-free
        #pragma unroll
        for (int r = 0; r < 8; r++) Es[(r0 + r) * 132 + m] = val[r];
        __syncthreads();
        #pragma unroll
        for (int it = 0; it < 2; it++) {
            int idx = t + it * 512;        // 1024 float4
            int g = idx >> 5, kl = idx & 31;
            float4 o = *(const float4*)&Es[kl * 132 + g * 4];
            *(float4*)&g_Ec4[((size_t)(b * 32 + g) * DD + d0 + kl) * 4] = o;
        }
    }
}

// ---------------------------------------------------------------------------
// Kernel 2 (PDL secondary): grid = 1024 (b x 64 jg x 2 kt), 128 threads,
// occ 8 (single wave). Thread = 1 k, 4 j. Ec streamed via cp.async 8-deep
// smem ring (7-stage prefetch > L2 latency). 4-way rational combine:
// 1 rcp / 4 m. Output via smem transpose -> coalesced STG.128.
// ---------------------------------------------------------------------------
__global__ void __launch_bounds__(128, 8) k2_pairwise(
    const float* __restrict__ v,
    float* __restrict__ out)
{
    __shared__ __align__(16) float4 ring[8 * 128];   // Ec stage ring (16KB)
    __shared__ __align__(16) float4 EaTf4[DIM];      // [m] -> (a_j0..a_j3)
    __shared__ __align__(16) float2 vD[DIM];         // duplicated v

    const int t   = threadIdx.x;
    const int bid = blockIdx.x;
    const int kt  = bid & 1;
    const int jg  = (bid >> 1) & 63;
    const int b   = bid >> 7;
    const int j0  = jg * 4;
    const int k   = kt * 128 + t;

    {   // k1-independent prologue (overlaps k1 under PDL)
        float vv = v[t];
        vD[t] = make_float2(vv, vv);
    }

    cudaGridDependencySynchronize();       // wait for k1 results

    EaTf4[t] = *(const float4*)&g_EaT[(size_t)(b * DIM + t) * DD + j0];

    const float4* ecq = (const float4*)g_Ec4 + (size_t)(b * 32) * DD + k;
    unsigned rb = (unsigned)__cvta_generic_to_shared(ring) + t * 16;

    #pragma unroll
    for (int s = 0; s < 7; s++) {          // prologue: stages 0..6
        cp16(rb + (s & 7) * 2048, ecq + (size_t)s * DD);
        cp_commit();
    }
    __syncthreads();                       // EaTf4 / vD visible

    const float Vsum = g_Vsum;
    const ull ONE2 = dup2(1.0f);
    ull acc0 = dup2(0.0f), acc1 = dup2(0.0f);

    #pragma unroll 8
    for (int g = 0; g < 32; g++) {
        cp_wait<6>();                      // stage g complete
        float4 E = ring[(g & 7) * 128 + t];

        ull ec0 = dup2(E.x), ec1 = dup2(E.y), ec2 = dup2(E.z), ec3 = dup2(E.w);
        const ulonglong2* eap = (const ulonglong2*)(EaTf4 + 4 * g);
        ulonglong2 ea0 = eap[0], ea1 = eap[1], ea2 = eap[2], ea3 = eap[3];
        ulonglong2 vab = ((const ulonglong2*)vD)[2 * g];
        ulonglong2 vcd = ((const ulonglong2*)vD)[2 * g + 1];

        {   // j-pair (j0,j1)
            ull q0 = fma2(ea0.x, ec0, ONE2);
            ull q1 = fma2(ea1.x, ec1, ONE2);
            ull q2 = fma2(ea2.x, ec2, ONE2);
            ull q3 = fma2(ea3.x, ec3, ONE2);
            ull d01 = mul2(q0, q1), d23 = mul2(q2, q3);
            ull n01 = mul2(vab.x, q1); n01 = fma2(vab.y, q0, n01);
            ull n23 = mul2(vcd.x, q3); n23 = fma2(vcd.y, q2, n23);
            ull den = mul2(d01, d23);
            ull num = mul2(n01, d23); num = fma2(n23, d01, num);
            float2 dd = unpk(den);
            ull rr = pk(frcp(dd.x), frcp(dd.y));
            acc0 = fma2(num, rr, acc0);
        }
        {   // j-pair (j2,j3)
            ull q0 = fma2(ea0.y, ec0, ONE2);
            ull q1 = fma2(ea1.y, ec1, ONE2);
            ull q2 = fma2(ea2.y, ec2, ONE2);
            ull q3 = fma2(ea3.y, ec3, ONE2);
            ull d01 = mul2(q0, q1), d23 = mul2(q2, q3);
            ull n01 = mul2(vab.x, q1); n01 = fma2(vab.y, q0, n01);
            ull n23 = mul2(vcd.x, q3); n23 = fma2(vcd.y, q2, n23);
            ull den = mul2(d01, d23);
            ull num = mul2(n01, d23); num = fma2(n23, d01, num);
            float2 dd = unpk(den);
            ull rr = pk(frcp(dd.x), frcp(dd.y));
            acc1 = fma2(num, rr, acc1);
        }

        if (g < 25) {                      // issue stage g+7 (guarded)
            cp16(rb + ((g + 7) & 7) * 2048, ecq + (size_t)(g + 7) * DD);
        }
        cp_commit();
    }

    // Output: transpose through ring (all cp.async groups drained) -> STG.128
    cp_wait<0>();
    __syncthreads();
    float* Os = (float*)ring;              // 4 j x 128 k = 2KB
    float2 a0 = unpk(acc0), a1 = unpk(acc1);
    Os[0 * 128 + t] = fmaf(-2.0f, a0.x, Vsum);
    Os[1 * 128 + t] = fmaf(-2.0f, a0.y, Vsum);
    Os[2 * 128 + t] = fmaf(-2.0f, a1.x, Vsum);
    Os[3 * 128 + t] = fmaf(-2.0f, a1.y, Vsum);
    __syncthreads();
    {
        int j = t >> 5, kq = t & 31;
        float4 o = *(const float4*)&Os[j * 128 + kq * 4];
        *(float4*)&out[(size_t)(b * DD + j0 + j) * DD + kt * 128 + kq * 4] = o;
    }
}

// ---------------------------------------------------------------------------
extern "C" void kernel_launch(void* const* d_in, const int* in_sizes, int n_in,
                              void* d_out, int out_size)
{
    const float* X  = (const float*)d_in[0];
    const float* W1 = (const float*)d_in[1];
    const float* W2 = (const float*)d_in[2];
    const float* v  = (const float*)d_in[3];
    float* out      = (float*)d_out;

    cudaFuncSetAttribute(k1_gemm_exp,
                         cudaFuncAttributeMaxDynamicSharedMemorySize, K1_SMEM);

    k1_gemm_exp<<<128, 512, K1_SMEM>>>(X, W1, W2, v);

    // PDL secondary launch: overlap k2's launch/prologue with k1.
    cudaLaunchAttribute attr[1];
    attr[0].id = cudaLaunchAttributeProgrammaticStreamSerialization;
    attr[0].val.programmaticStreamSerializationAllowed = 1;
    cudaLaunchConfig_t cfg = {};
    cfg.gridDim  = dim3(1024, 1, 1);
    cfg.blockDim = dim3(128, 1, 1);
    cfg.dynamicSmemBytes = 0;
    cfg.stream = 0;
    cfg.attrs = attr;
    cfg.numAttrs = 1;
    cudaLaunchKernelEx(&cfg, k2_pairwise, v, out);
}